// round 12
// baseline (speedup 1.0000x reference)
#include <cuda_runtime.h>
#include <cuda_bf16.h>
#include <cuda_fp16.h>
#include <cstdint>

#define NPIX 4096
#define CIN  512
#define DK   64
#define BAT  4
#define NSPL 32   // chan_e N-splits

// ---------------- scratch ----------------
__device__ __nv_bfloat16 g_qb[BAT * DK * NPIX];
__device__ __nv_bfloat16 g_kb[BAT * DK * NPIX];
__device__ __nv_bfloat16 g_vbf[BAT * CIN * NPIX];
__device__ float g_p[BAT * DK * NPIX];
__device__ __half g_e16[(size_t)BAT * NPIX * NPIX];           // fp16 energy
__device__ __nv_bfloat16 g_attnb[(size_t)BAT * NPIX * NPIX];  // bf16 attn
__device__ __nv_bfloat16 g_Wb[640 * 512];
__device__ float g_ball[640];
__device__ __nv_bfloat16 g_xh[BAT * CIN * NPIX];
__device__ float g_epart[NSPL * BAT * DK * DK];

// ---------------- helpers ----------------
__device__ __forceinline__ uint32_t smem_u32(const void* p) {
    uint32_t a;
    asm("{ .reg .u64 t; cvta.to.shared.u64 t, %1; cvt.u32.u64 %0, t; }" : "=r"(a) : "l"(p));
    return a;
}
__device__ __forceinline__ void ldm_x4(uint32_t r[4], uint32_t addr) {
    asm volatile("ldmatrix.sync.aligned.m8n8.x4.shared.b16 {%0,%1,%2,%3}, [%4];"
                 : "=r"(r[0]), "=r"(r[1]), "=r"(r[2]), "=r"(r[3]) : "r"(addr));
}
__device__ __forceinline__ void ldm_x4t(uint32_t r[4], uint32_t addr) {
    asm volatile("ldmatrix.sync.aligned.m8n8.x4.trans.shared.b16 {%0,%1,%2,%3}, [%4];"
                 : "=r"(r[0]), "=r"(r[1]), "=r"(r[2]), "=r"(r[3]) : "r"(addr));
}
__device__ __forceinline__ void mma16816(float c[4], const uint32_t a[4], uint32_t b0, uint32_t b1) {
    asm volatile("mma.sync.aligned.m16n8k16.row.col.f32.bf16.bf16.f32 "
                 "{%0,%1,%2,%3}, {%4,%5,%6,%7}, {%8,%9}, {%0,%1,%2,%3};"
                 : "+f"(c[0]), "+f"(c[1]), "+f"(c[2]), "+f"(c[3])
                 : "r"(a[0]), "r"(a[1]), "r"(a[2]), "r"(a[3]), "r"(b0), "r"(b1));
}
__device__ __forceinline__ void cp16(uint32_t dst, const void* src) {
    asm volatile("cp.async.cg.shared.global [%0], [%1], 16;" :: "r"(dst), "l"(src) : "memory");
}
#define CP_COMMIT() asm volatile("cp.async.commit_group;" ::: "memory")
#define CP_WAIT1()  asm volatile("cp.async.wait_group 1;" ::: "memory")
#define CP_WAIT0()  asm volatile("cp.async.wait_group 0;" ::: "memory")

// ---------------- pack weights + convert x (merged) ----------------
__global__ void packx_kernel(const float* __restrict__ x,
                             const float* __restrict__ Wq, const float* __restrict__ bq,
                             const float* __restrict__ Wk, const float* __restrict__ bk,
                             const float* __restrict__ Wv, const float* __restrict__ bv) {
    int idx = blockIdx.x * blockDim.x + threadIdx.x;
    float4 v = *(const float4*)&x[(size_t)idx * 4];
    __nv_bfloat162 h0 = __floats2bfloat162_rn(v.x, v.y);
    __nv_bfloat162 h1 = __floats2bfloat162_rn(v.z, v.w);
    uint2 pk;
    pk.x = *(uint32_t*)&h0; pk.y = *(uint32_t*)&h1;
    *(uint2*)&g_xh[(size_t)idx * 4] = pk;
    if (idx < 640 * 512) {
        int o = idx >> 9, c = idx & 511;
        float w;
        if (o < 64)       w = Wq[o * 512 + c];
        else if (o < 128) w = Wk[(o - 64) * 512 + c];
        else              w = Wv[(o - 128) * 512 + c];
        g_Wb[idx] = __float2bfloat16(w);
    }
    if (idx < 640) {
        float w;
        if (idx < 64)       w = bq[idx];
        else if (idx < 128) w = bk[idx - 64];
        else                w = bv[idx - 128];
        g_ball[idx] = w;
    }
}

// ---------------- proj q/k/v via bf16 HMMA: 4 warps, 64x64 warp tiles ----------------
#define PW_STRIDE 72
#define PX_STRIDE 136
#define PW_BYTES (128 * PW_STRIDE * 2)
#define PX_BYTES (64 * PX_STRIDE * 2)
#define PSTAGE   (PW_BYTES + PX_BYTES)
__global__ __launch_bounds__(128) void projqkv_kernel() {
    extern __shared__ __align__(16) char smem[];
    uint32_t sb = smem_u32(smem);
    int b = blockIdx.z;
    int n0 = blockIdx.x * 128;
    int o0 = blockIdx.y * 128;
    int t = threadIdx.x, lane = t & 31, wid = t >> 5;
    int warpM = wid & 1, warpN = wid >> 1;
    int lrow = lane & 15, lhalf = lane >> 4;
    const __nv_bfloat16* xb = g_xh + (size_t)b * CIN * NPIX;
    float acc[4][8][4] = {};

#define PQ_ISSUE(kb) do { \
        uint32_t base = sb + ((kb) & 1) * PSTAGE; \
        for (int it = 0; it < 8; it++) { \
            int g = t + it * 128; \
            int row = g >> 3, cc = (g & 7) * 8; \
            cp16(base + row * (PW_STRIDE * 2) + cc * 2, \
                 g_Wb + (size_t)(o0 + row) * 512 + (kb) * 64 + cc); \
        } \
        for (int it = 0; it < 8; it++) { \
            int g = t + it * 128; \
            int row = g >> 4, cc = (g & 15) * 8; \
            cp16(base + PW_BYTES + row * (PX_STRIDE * 2) + cc * 2, \
                 xb + (size_t)((kb) * 64 + row) * NPIX + n0 + cc); \
        } \
        CP_COMMIT(); \
    } while (0)

    PQ_ISSUE(0);
    int dbase = ((lane >> 4) << 3) + (lane & 7);
    int coladd = ((lane >> 3) & 1) * 8;
    for (int kb = 0; kb < 8; kb++) {
        if (kb < 7) { PQ_ISSUE(kb + 1); CP_WAIT1(); } else CP_WAIT0();
        __syncthreads();
        uint32_t base = sb + (kb & 1) * PSTAGE;
        uint32_t wB = base, xB = base + PW_BYTES;
#pragma unroll
        for (int ks = 0; ks < 4; ks++) {
            uint32_t afr[4][4];
#pragma unroll
            for (int mi = 0; mi < 4; mi++) {
                int row = warpM * 64 + mi * 16 + lrow;
                ldm_x4(afr[mi], wB + row * (PW_STRIDE * 2) + ks * 32 + lhalf * 16);
            }
            int drow = ks * 16 + dbase;
#pragma unroll
            for (int ng = 0; ng < 4; ng++) {
                uint32_t bfr[4];
                ldm_x4t(bfr, xB + drow * (PX_STRIDE * 2) + (warpN * 64 + ng * 16 + coladd) * 2);
#pragma unroll
                for (int mi = 0; mi < 4; mi++) {
                    mma16816(acc[mi][2 * ng],     afr[mi], bfr[0], bfr[2]);
                    mma16816(acc[mi][2 * ng + 1], afr[mi], bfr[1], bfr[3]);
                }
            }
        }
        __syncthreads();
    }
#pragma unroll
    for (int mi = 0; mi < 4; mi++) {
        int row_lo = o0 + warpM * 64 + mi * 16 + (lane >> 2);
        int row_hi = row_lo + 8;
        float bl = g_ball[row_lo], bh = g_ball[row_hi];
        __nv_bfloat16* dlo;
        __nv_bfloat16* dhi;
        if (row_lo < 64)       dlo = g_qb + ((size_t)b * DK + row_lo) * NPIX;
        else if (row_lo < 128) dlo = g_kb + ((size_t)b * DK + row_lo - 64) * NPIX;
        else                   dlo = g_vbf + ((size_t)b * CIN + row_lo - 128) * NPIX;
        if (row_hi < 64)       dhi = g_qb + ((size_t)b * DK + row_hi) * NPIX;
        else if (row_hi < 128) dhi = g_kb + ((size_t)b * DK + row_hi - 64) * NPIX;
        else                   dhi = g_vbf + ((size_t)b * CIN + row_hi - 128) * NPIX;
#pragma unroll
        for (int ni = 0; ni < 8; ni++) {
            int col = n0 + warpN * 64 + ni * 8 + (lane & 3) * 2;
            __nv_bfloat162 h0 = __floats2bfloat162_rn(acc[mi][ni][0] + bl, acc[mi][ni][1] + bl);
            __nv_bfloat162 h1 = __floats2bfloat162_rn(acc[mi][ni][2] + bh, acc[mi][ni][3] + bh);
            *(uint32_t*)(dlo + col) = *(uint32_t*)&h0;
            *(uint32_t*)(dhi + col) = *(uint32_t*)&h1;
        }
    }
}

// ---------------- proj p (xd) fp32 ----------------
__global__ __launch_bounds__(256) void proj_p_kernel(const float* __restrict__ x,
                                                     const float* __restrict__ Wd,
                                                     const float* __restrict__ bd) {
    int b = blockIdx.z;
    int n0 = blockIdx.x * 128;
    const float* B = x + (size_t)b * CIN * NPIX;
    __shared__ float As[8][64];
    __shared__ float Bs[8][128];
    int t = threadIdx.x;
    int tx = t & 15, ty = t >> 4;
    float acc[4][8] = {};
    for (int k0 = 0; k0 < 512; k0 += 8) {
        float4 a4 = make_float4(0.f, 0.f, 0.f, 0.f);
        int arow = t >> 1, akq = (t & 1) * 4;
        if (t < 128) a4 = *(const float4*)&Wd[arow * 512 + k0 + akq];
        int bk = t >> 5, bnq = (t & 31) * 4;
        float4 b4 = *(const float4*)&B[(size_t)(k0 + bk) * NPIX + n0 + bnq];
        __syncthreads();
        if (t < 128) {
            As[akq + 0][arow] = a4.x; As[akq + 1][arow] = a4.y;
            As[akq + 2][arow] = a4.z; As[akq + 3][arow] = a4.w;
        }
        *(float4*)&Bs[bk][bnq] = b4;
        __syncthreads();
#pragma unroll
        for (int k = 0; k < 8; k++) {
            float a[4], bb[8];
#pragma unroll
            for (int i = 0; i < 4; i++) a[i] = As[k][ty * 4 + i];
            *(float4*)&bb[0] = *(float4*)&Bs[k][tx * 8];
            *(float4*)&bb[4] = *(float4*)&Bs[k][tx * 8 + 4];
#pragma unroll
            for (int i = 0; i < 4; i++)
#pragma unroll
                for (int j = 0; j < 8; j++) acc[i][j] += a[i] * bb[j];
        }
    }
#pragma unroll
    for (int i = 0; i < 4; i++) {
        int row = ty * 4 + i;
        float bias = bd[row];
        float* dst = g_p + ((size_t)b * DK + row) * NPIX + n0 + tx * 8;
#pragma unroll
        for (int j = 0; j < 8; j++) dst[j] = acc[i][j] + bias;
    }
}

// ---------------- energy via bf16 HMMA -> fp16 E: 4 warps, 64x64 tiles ----------------
__global__ __launch_bounds__(128) void energy_hmma_kernel() {
    __shared__ __align__(16) __nv_bfloat16 Qs[64 * 136];
    __shared__ __align__(16) __nv_bfloat16 Ks[64 * 136];
    int b = blockIdx.z, j0 = blockIdx.x * 128, i0 = blockIdx.y * 128;
    int t = threadIdx.x, lane = t & 31, wid = t >> 5;
    int warpM = wid & 1, warpN = wid >> 1;
    const __nv_bfloat16* qp = g_qb + (size_t)b * DK * NPIX;
    const __nv_bfloat16* kp = g_kb + (size_t)b * DK * NPIX;
    uint32_t sQ = smem_u32(Qs), sK = smem_u32(Ks);
#pragma unroll
    for (int it = 0; it < 8; it++) {
        int g = t + it * 128;
        int row = g >> 4, cc = (g & 15) * 8;
        cp16(sQ + row * 272 + cc * 2, qp + (size_t)row * NPIX + i0 + cc);
        cp16(sK + row * 272 + cc * 2, kp + (size_t)row * NPIX + j0 + cc);
    }
    CP_COMMIT();
    CP_WAIT0();
    __syncthreads();

    float acc[4][8][4] = {};
    int dbase = ((lane >> 4) << 3) + (lane & 7);
    int coladd = ((lane >> 3) & 1) * 8;
#pragma unroll
    for (int ks = 0; ks < 4; ks++) {
        int drow = ks * 16 + dbase;
        uint32_t afr[4][4];
#pragma unroll
        for (int mi = 0; mi < 4; mi++)
            ldm_x4t(afr[mi], sQ + drow * 272 + (warpM * 64 + mi * 16 + coladd) * 2);
#pragma unroll
        for (int ng = 0; ng < 4; ng++) {
            uint32_t bfr[4];
            ldm_x4t(bfr, sK + drow * 272 + (warpN * 64 + ng * 16 + coladd) * 2);
#pragma unroll
            for (int mi = 0; mi < 4; mi++) {
                mma16816(acc[mi][2 * ng],     afr[mi], bfr[0], bfr[2]);
                mma16816(acc[mi][2 * ng + 1], afr[mi], bfr[1], bfr[3]);
            }
        }
    }
    __half* Eb = g_e16 + (size_t)b * NPIX * NPIX;
#pragma unroll
    for (int mi = 0; mi < 4; mi++) {
        int row = i0 + warpM * 64 + mi * 16 + (lane >> 2);
#pragma unroll
        for (int ni = 0; ni < 8; ni++) {
            int col = j0 + warpN * 64 + ni * 8 + (lane & 3) * 2;
            __half2 h0 = __floats2half2_rn(acc[mi][ni][0], acc[mi][ni][1]);
            __half2 h1 = __floats2half2_rn(acc[mi][ni][2], acc[mi][ni][3]);
            *(uint32_t*)&Eb[(size_t)row * NPIX + col]       = *(uint32_t*)&h0;
            *(uint32_t*)&Eb[(size_t)(row + 8) * NPIX + col] = *(uint32_t*)&h1;
        }
    }
}

// ---------------- softmax: fp16 in, bf16 out ----------------
__device__ __forceinline__ float blkRedMax(float v, float* red) {
#pragma unroll
    for (int o = 16; o > 0; o >>= 1) v = fmaxf(v, __shfl_xor_sync(0xffffffffu, v, o));
    if ((threadIdx.x & 31) == 0) red[threadIdx.x >> 5] = v;
    __syncthreads();
    float r = (threadIdx.x < 8) ? red[threadIdx.x] : -1e30f;
    if (threadIdx.x < 32) {
#pragma unroll
        for (int o = 4; o > 0; o >>= 1) r = fmaxf(r, __shfl_xor_sync(0xffffffffu, r, o));
        if (threadIdx.x == 0) red[0] = r;
    }
    __syncthreads();
    float res = red[0];
    __syncthreads();
    return res;
}
__device__ __forceinline__ float blkRedSum(float v, float* red) {
#pragma unroll
    for (int o = 16; o > 0; o >>= 1) v += __shfl_xor_sync(0xffffffffu, v, o);
    if ((threadIdx.x & 31) == 0) red[threadIdx.x >> 5] = v;
    __syncthreads();
    float r = (threadIdx.x < 8) ? red[threadIdx.x] : 0.f;
    if (threadIdx.x < 32) {
#pragma unroll
        for (int o = 4; o > 0; o >>= 1) r += __shfl_xor_sync(0xffffffffu, r, o);
        if (threadIdx.x == 0) red[0] = r;
    }
    __syncthreads();
    float res = red[0];
    __syncthreads();
    return res;
}

__global__ __launch_bounds__(256) void softmax_kernel() {
    int i = blockIdx.x, b = blockIdx.y;
    const __half* row = g_e16 + ((size_t)b * NPIX + i) * NPIX;
    __nv_bfloat16* orow = g_attnb + ((size_t)b * NPIX + i) * NPIX;
    int t = threadIdx.x;
    __shared__ float red[8];

    float4 v[4];
    float mx = -1e30f;
#pragma unroll
    for (int j = 0; j < 4; j++) {
        uint2 pk = *(const uint2*)&row[t * 4 + 1024 * j];
        __half2 a = *(__half2*)&pk.x;
        __half2 bq = *(__half2*)&pk.y;
        float2 f0 = __half22float2(a);
        float2 f1 = __half22float2(bq);
        v[j] = make_float4(f0.x, f0.y, f1.x, f1.y);
        mx = fmaxf(mx, fmaxf(fmaxf(v[j].x, v[j].y), fmaxf(v[j].z, v[j].w)));
    }
    float rmax = blkRedMax(mx, red);
    float s = 0.f;
#pragma unroll
    for (int j = 0; j < 4; j++) {
        v[j].x = __expf(v[j].x - rmax); v[j].y = __expf(v[j].y - rmax);
        v[j].z = __expf(v[j].z - rmax); v[j].w = __expf(v[j].w - rmax);
        s += v[j].x + v[j].y + v[j].z + v[j].w;
    }
    float inv = 1.f / blkRedSum(s, red);
#pragma unroll
    for (int j = 0; j < 4; j++) {
        __nv_bfloat162 h0 = __floats2bfloat162_rn(v[j].x * inv, v[j].y * inv);
        __nv_bfloat162 h1 = __floats2bfloat162_rn(v[j].z * inv, v[j].w * inv);
        uint2 pk;
        pk.x = *(uint32_t*)&h0; pk.y = *(uint32_t*)&h1;
        *(uint2*)&orow[t * 4 + 1024 * j] = pk;
    }
}

// ---------------- s_out: 4 warps, 64x64 warp tiles, c-inner grid for L2 reuse ----------------
#define SO_STRIDE 72
#define SO_TILE   (128 * SO_STRIDE * 2)   // 18432
#define SO_STAGE  (2 * SO_TILE)           // 36864
__global__ __launch_bounds__(128) void sout_kernel(const float* __restrict__ x,
                                                   const float* __restrict__ gamma_s,
                                                   float* __restrict__ out) {
    extern __shared__ __align__(16) char smem[];
    uint32_t sb = smem_u32(smem);
    int b = blockIdx.z;
    int m0 = blockIdx.y * 128;
    int c0 = blockIdx.x * 128;
    int t = threadIdx.x, lane = t & 31, wid = t >> 5;
    int warpM = wid & 1, warpN = wid >> 1;
    int lrow = lane & 15, lhalf = lane >> 4;
    const __nv_bfloat16* vb = g_vbf   + (size_t)b * CIN  * NPIX;
    const __nv_bfloat16* ab = g_attnb + (size_t)b * NPIX * NPIX;
    float acc[4][8][4] = {};

#define SO_ISSUE(kb) do { \
        uint32_t base = sb + ((kb) & 1) * SO_STAGE; \
        for (int it = 0; it < 8; it++) { \
            int g = t + it * 128; \
            int row = g >> 3, cc = (g & 7) * 8; \
            cp16(base + row * (SO_STRIDE * 2) + cc * 2, \
                 vb + (size_t)(c0 + row) * NPIX + (kb) * 64 + cc); \
        } \
        for (int it = 0; it < 8; it++) { \
            int g = t + it * 128; \
            int row = g >> 3, cc = (g & 7) * 8; \
            cp16(base + SO_TILE + row * (SO_STRIDE * 2) + cc * 2, \
                 ab + (size_t)(m0 + row) * NPIX + (kb) * 64 + cc); \
        } \
        CP_COMMIT(); \
    } while (0)

    SO_ISSUE(0);
    for (int kb = 0; kb < 64; kb++) {
        if (kb < 63) { SO_ISSUE(kb + 1); CP_WAIT1(); } else CP_WAIT0();
        __syncthreads();
        uint32_t base = sb + (kb & 1) * SO_STAGE;
        uint32_t aB = base, bB = base + SO_TILE;
#pragma unroll
        for (int ks = 0; ks < 4; ks++) {
            uint32_t afr[4][4];
#pragma unroll
            for (int mi = 0; mi < 4; mi++) {
                int row = warpM * 64 + mi * 16 + lrow;
                ldm_x4(afr[mi], aB + row * (SO_STRIDE * 2) + ks * 32 + lhalf * 16);
            }
#pragma unroll
            for (int ng = 0; ng < 4; ng++) {
                int row = warpN * 64 + ng * 16 + lrow;
                uint32_t bfr[4];
                ldm_x4(bfr, bB + row * (SO_STRIDE * 2) + ks * 32 + lhalf * 16);
#pragma unroll
                for (int mi = 0; mi < 4; mi++) {
                    mma16816(acc[mi][2 * ng],     afr[mi], bfr[0], bfr[2]);
                    mma16816(acc[mi][2 * ng + 1], afr[mi], bfr[1], bfr[3]);
                }
            }
        }
        __syncthreads();
    }

    float gs = *gamma_s;
    const float* xb = x   + (size_t)b * CIN * NPIX;
    float*       ob = out + (size_t)b * CIN * NPIX;
#pragma unroll
    for (int mi = 0; mi < 4; mi++) {
        int row = c0 + warpM * 64 + mi * 16 + (lane >> 2);
#pragma unroll
        for (int ni = 0; ni < 8; ni++) {
            int col = m0 + warpN * 64 + ni * 8 + (lane & 3) * 2;
            size_t i0 = (size_t)row * NPIX + col;
            float2 x0 = *(const float2*)&xb[i0];
            float2 o0 = make_float2(gs * acc[mi][ni][0] + x0.x, gs * acc[mi][ni][1] + x0.y);
            *(float2*)&ob[i0] = o0;
            size_t i1 = i0 + (size_t)8 * NPIX;
            float2 x1 = *(const float2*)&xb[i1];
            float2 o1 = make_float2(gs * acc[mi][ni][2] + x1.x, gs * acc[mi][ni][3] + x1.y);
            *(float2*)&ob[i1] = o1;
        }
    }
}

// ---------------- chan_e: e partials (fp32), 32 N-splits ----------------
__global__ __launch_bounds__(256) void chan_e_kernel() {
    int b = blockIdx.y, kb = blockIdx.x;
    const float* p = g_p + (size_t)b * DK * NPIX;
    __shared__ float sp[64][65];
    int t = threadIdx.x;
    int tx = t & 15, ty = t >> 4;
    float acc[4][4] = {};
    for (int ch = 0; ch < 2; ch++) {
        int base = kb * 128 + ch * 64;
        __syncthreads();
#pragma unroll
        for (int i = 0; i < 16; i++) {
            int lin = t + 256 * i;
            int r = lin >> 6, c = lin & 63;
            sp[c][r] = p[(size_t)r * NPIX + base + c];
        }
        __syncthreads();
#pragma unroll 8
        for (int k = 0; k < 64; k++) {
            float a[4], bb[4];
#pragma unroll
            for (int i = 0; i < 4; i++) a[i]  = sp[k][ty * 4 + i];
#pragma unroll
            for (int j = 0; j < 4; j++) bb[j] = sp[k][tx * 4 + j];
#pragma unroll
            for (int i = 0; i < 4; i++)
#pragma unroll
                for (int j = 0; j < 4; j++) acc[i][j] += a[i] * bb[j];
        }
    }
#pragma unroll
    for (int i = 0; i < 4; i++)
#pragma unroll
        for (int j = 0; j < 4; j++)
            g_epart[(((size_t)kb * BAT + b) * DK + ty * 4 + i) * DK + tx * 4 + j] = acc[i][j];
}

// ---------------- chanfinal: cattn softmax + cf + Wu GEMM + out+=, fused ----------------
#define CF_CA   0
#define CF_BUF  16640
#define CF_CF   (16640 + 33792)
#define CF_SMEM (16640 + 33792 + 33792)
__global__ __launch_bounds__(256) void chanfinal_kernel(const float* __restrict__ Wu,
                                                        const float* __restrict__ bu,
                                                        const float* __restrict__ gamma_c,
                                                        float* __restrict__ out) {
    extern __shared__ __align__(16) char cs[];
    float* ca  = (float*)(cs + CF_CA);
    float* buf = (float*)(cs + CF_BUF);
    float* cf  = (float*)(cs + CF_CF);
    int b = blockIdx.y;
    int n0 = blockIdx.x * 128;
    int t = threadIdx.x;
    int w = t >> 5, lane = t & 31;
    const float* p = g_p + (size_t)b * DK * NPIX;

    for (int r = w * 8; r < w * 8 + 8; r++) {
        float v0 = 0.f, v1 = 0.f;
        for (int kb = 0; kb < NSPL; kb++) {
            const float* ep = &g_epart[(((size_t)kb * BAT + b) * DK + r) * DK];
            v0 += ep[lane];
            v1 += ep[lane + 32];
        }
        float mn = fminf(v0, v1);
#pragma unroll
        for (int o = 16; o > 0; o >>= 1) mn = fminf(mn, __shfl_xor_sync(0xffffffffu, mn, o));
        float z0 = __expf(mn - v0), z1 = __expf(mn - v1);
        float s = z0 + z1;
#pragma unroll
        for (int o = 16; o > 0; o >>= 1) s += __shfl_xor_sync(0xffffffffu, s, o);
        float inv = 1.f / s;
        ca[lane * 65 + r]        = z0 * inv;
        ca[(lane + 32) * 65 + r] = z1 * inv;
    }
    for (int i = t; i < 64 * 128; i += 256) {
        int d = i >> 7, n = i & 127;
        buf[d * 132 + n] = p[(size_t)d * NPIX + n0 + n];
    }
    __syncthreads();
    {
        int tx = t & 15, ty = t >> 4;
        float acc[4][8] = {};
        for (int k = 0; k < 64; k++) {
            float a[4], bb[8];
#pragma unroll
            for (int i = 0; i < 4; i++) a[i] = ca[k * 65 + ty * 4 + i];
#pragma unroll
            for (int j = 0; j < 8; j++) bb[j] = buf[k * 132 + tx * 8 + j];
#pragma unroll
            for (int i = 0; i < 4; i++)
#pragma unroll
                for (int j = 0; j < 8; j++) acc[i][j] += a[i] * bb[j];
        }
        float gc = *gamma_c;
#pragma unroll
        for (int i = 0; i < 4; i++) {
            int c = ty * 4 + i;
#pragma unroll
            for (int j = 0; j < 8; j++) {
                int n = tx * 8 + j;
                cf[c * 132 + n] = gc * acc[i][j] + buf[c * 132 + n];
            }
        }
    }
    __syncthreads();
    for (int ch = 0; ch < 4; ch++) {
        for (int i = t; i < 128 * 64; i += 256) {
            int o = i >> 6, k = i & 63;
            buf[k * 132 + o] = Wu[(size_t)(ch * 128 + o) * DK + k];
        }
        __syncthreads();
        int tx = t & 15, ty = t >> 4;
        float acc[8][8] = {};
        for (int k = 0; k < 64; k++) {
            float a[8], bb[8];
#pragma unroll
            for (int i = 0; i < 8; i++) a[i]  = buf[k * 132 + ty * 8 + i];
#pragma unroll
            for (int j = 0; j < 8; j++) bb[j] = cf[k * 132 + tx * 8 + j];
#pragma unroll
            for (int i = 0; i < 8; i++)
#pragma unroll
                for (int j = 0; j < 8; j++) acc[i][j] += a[i] * bb[j];
        }
#pragma unroll
        for (int i = 0; i < 8; i++) {
            int o = ch * 128 + ty * 8 + i;
            float bias = bu[o];
            size_t base = ((size_t)b * CIN + o) * NPIX + n0 + tx * 8;
            float4 c0 = *(float4*)&out[base];
            float4 c1 = *(float4*)&out[base + 4];
            c0.x += acc[i][0] + bias; c0.y += acc[i][1] + bias;
            c0.z += acc[i][2] + bias; c0.w += acc[i][3] + bias;
            c1.x += acc[i][4] + bias; c1.y += acc[i][5] + bias;
            c1.z += acc[i][6] + bias; c1.w += acc[i][7] + bias;
            *(float4*)&out[base]     = c0;
            *(float4*)&out[base + 4] = c1;
        }
        __syncthreads();
    }
}

// ---------------- launch ----------------
extern "C" void kernel_launch(void* const* d_in, const int* in_sizes, int n_in,
                              void* d_out, int out_size) {
    const float* x  = (const float*)d_in[0];
    const float* Wq = (const float*)d_in[1];
    const float* bq = (const float*)d_in[2];
    const float* Wk = (const float*)d_in[3];
    const float* bk = (const float*)d_in[4];
    const float* Wv = (const float*)d_in[5];
    const float* bv = (const float*)d_in[6];
    const float* gs = (const float*)d_in[7];
    const float* Wd = (const float*)d_in[8];
    const float* bd = (const float*)d_in[9];
    const float* Wu = (const float*)d_in[10];
    const float* bu = (const float*)d_in[11];
    const float* gc = (const float*)d_in[12];
    float* out = (float*)d_out;

    cudaFuncSetAttribute(projqkv_kernel, cudaFuncAttributeMaxDynamicSharedMemorySize, 2 * PSTAGE);
    cudaFuncSetAttribute(sout_kernel, cudaFuncAttributeMaxDynamicSharedMemorySize, 2 * SO_STAGE);
    cudaFuncSetAttribute(chanfinal_kernel, cudaFuncAttributeMaxDynamicSharedMemorySize, CF_SMEM);

    packx_kernel<<<8192, 256>>>(x, Wq, bq, Wk, bk, Wv, bv);
    proj_p_kernel<<<dim3(32, 1, BAT), 256>>>(x, Wd, bd);
    projqkv_kernel<<<dim3(32, 5, BAT), 128, 2 * PSTAGE>>>();
    chan_e_kernel<<<dim3(NSPL, BAT), 256>>>();
    energy_hmma_kernel<<<dim3(32, 32, BAT), 128>>>();
    softmax_kernel<<<dim3(NPIX, BAT), 256>>>();
    sout_kernel<<<dim3(4, 32, BAT), 128, 2 * SO_STAGE>>>(x, gs, out);
    chanfinal_kernel<<<dim3(32, BAT), 256, CF_SMEM>>>(Wu, bu, gc, out);
}

// round 13
// speedup vs baseline: 1.0456x; 1.0456x over previous
#include <cuda_runtime.h>
#include <cuda_bf16.h>
#include <cuda_fp16.h>
#include <cstdint>

#define NPIX 4096
#define CIN  512
#define DK   64
#define BAT  4
#define NSPL 32   // chan_e N-splits

// ---------------- scratch ----------------
__device__ __nv_bfloat16 g_qb[BAT * DK * NPIX];
__device__ __nv_bfloat16 g_kb[BAT * DK * NPIX];
__device__ __half g_vh16[BAT * CIN * NPIX];                  // v fp16
__device__ float g_p[BAT * DK * NPIX];
__device__ __half g_e16[(size_t)BAT * NPIX * NPIX];          // fp16 energy
__device__ __half g_attnh[(size_t)BAT * NPIX * NPIX];        // fp16 attn
__device__ __nv_bfloat16 g_Wb[640 * 512];
__device__ float g_ball[640];
__device__ __nv_bfloat16 g_xh[BAT * CIN * NPIX];
__device__ float g_epart[NSPL * BAT * DK * DK];

// ---------------- helpers ----------------
__device__ __forceinline__ uint32_t smem_u32(const void* p) {
    uint32_t a;
    asm("{ .reg .u64 t; cvta.to.shared.u64 t, %1; cvt.u32.u64 %0, t; }" : "=r"(a) : "l"(p));
    return a;
}
__device__ __forceinline__ void ldm_x4(uint32_t r[4], uint32_t addr) {
    asm volatile("ldmatrix.sync.aligned.m8n8.x4.shared.b16 {%0,%1,%2,%3}, [%4];"
                 : "=r"(r[0]), "=r"(r[1]), "=r"(r[2]), "=r"(r[3]) : "r"(addr));
}
__device__ __forceinline__ void ldm_x4t(uint32_t r[4], uint32_t addr) {
    asm volatile("ldmatrix.sync.aligned.m8n8.x4.trans.shared.b16 {%0,%1,%2,%3}, [%4];"
                 : "=r"(r[0]), "=r"(r[1]), "=r"(r[2]), "=r"(r[3]) : "r"(addr));
}
__device__ __forceinline__ void mma16816(float c[4], const uint32_t a[4], uint32_t b0, uint32_t b1) {
    asm volatile("mma.sync.aligned.m16n8k16.row.col.f32.bf16.bf16.f32 "
                 "{%0,%1,%2,%3}, {%4,%5,%6,%7}, {%8,%9}, {%0,%1,%2,%3};"
                 : "+f"(c[0]), "+f"(c[1]), "+f"(c[2]), "+f"(c[3])
                 : "r"(a[0]), "r"(a[1]), "r"(a[2]), "r"(a[3]), "r"(b0), "r"(b1));
}
// fp16-accumulate HMMA (half the acc regs; possibly double rate)
__device__ __forceinline__ void mma16816h(uint32_t c[2], const uint32_t a[4], uint32_t b0, uint32_t b1) {
    asm volatile("mma.sync.aligned.m16n8k16.row.col.f16.f16.f16.f16 "
                 "{%0,%1}, {%2,%3,%4,%5}, {%6,%7}, {%0,%1};"
                 : "+r"(c[0]), "+r"(c[1])
                 : "r"(a[0]), "r"(a[1]), "r"(a[2]), "r"(a[3]), "r"(b0), "r"(b1));
}
__device__ __forceinline__ void cp16(uint32_t dst, const void* src) {
    asm volatile("cp.async.cg.shared.global [%0], [%1], 16;" :: "r"(dst), "l"(src) : "memory");
}
#define CP_COMMIT() asm volatile("cp.async.commit_group;" ::: "memory")
#define CP_WAIT1()  asm volatile("cp.async.wait_group 1;" ::: "memory")
#define CP_WAIT0()  asm volatile("cp.async.wait_group 0;" ::: "memory")

// ---------------- pack weights + convert x (merged) ----------------
__global__ void packx_kernel(const float* __restrict__ x,
                             const float* __restrict__ Wq, const float* __restrict__ bq,
                             const float* __restrict__ Wk, const float* __restrict__ bk,
                             const float* __restrict__ Wv, const float* __restrict__ bv) {
    int idx = blockIdx.x * blockDim.x + threadIdx.x;
    float4 v = *(const float4*)&x[(size_t)idx * 4];
    __nv_bfloat162 h0 = __floats2bfloat162_rn(v.x, v.y);
    __nv_bfloat162 h1 = __floats2bfloat162_rn(v.z, v.w);
    uint2 pk;
    pk.x = *(uint32_t*)&h0; pk.y = *(uint32_t*)&h1;
    *(uint2*)&g_xh[(size_t)idx * 4] = pk;
    if (idx < 640 * 512) {
        int o = idx >> 9, c = idx & 511;
        float w;
        if (o < 64)       w = Wq[o * 512 + c];
        else if (o < 128) w = Wk[(o - 64) * 512 + c];
        else              w = Wv[(o - 128) * 512 + c];
        g_Wb[idx] = __float2bfloat16(w);
    }
    if (idx < 640) {
        float w;
        if (idx < 64)       w = bq[idx];
        else if (idx < 128) w = bk[idx - 64];
        else                w = bv[idx - 128];
        g_ball[idx] = w;
    }
}

// ---------------- proj q/k/v via bf16 HMMA (round-11 proven: 8 warps) ----------------
#define PW_STRIDE 72
#define PX_STRIDE 136
#define PW_BYTES (128 * PW_STRIDE * 2)
#define PX_BYTES (64 * PX_STRIDE * 2)
#define PSTAGE   (PW_BYTES + PX_BYTES)
__global__ __launch_bounds__(256) void projqkv_kernel() {
    extern __shared__ __align__(16) char smem[];
    uint32_t sb = smem_u32(smem);
    int b = blockIdx.z;
    int n0 = blockIdx.x * 128;
    int o0 = blockIdx.y * 128;
    int t = threadIdx.x, lane = t & 31, wid = t >> 5;
    int warpM = wid & 3, warpN = wid >> 2;
    int lrow = lane & 15, lhalf = lane >> 4;
    const __nv_bfloat16* xb = g_xh + (size_t)b * CIN * NPIX;
    float acc[2][8][4] = {};

#define PQ_ISSUE(kb) do { \
        uint32_t base = sb + ((kb) & 1) * PSTAGE; \
        for (int it = 0; it < 4; it++) { \
            int g = t + it * 256; \
            int row = g >> 3, cc = (g & 7) * 8; \
            cp16(base + row * (PW_STRIDE * 2) + cc * 2, \
                 g_Wb + (size_t)(o0 + row) * 512 + (kb) * 64 + cc); \
        } \
        for (int it = 0; it < 4; it++) { \
            int g = t + it * 256; \
            int row = g >> 4, cc = (g & 15) * 8; \
            cp16(base + PW_BYTES + row * (PX_STRIDE * 2) + cc * 2, \
                 xb + (size_t)((kb) * 64 + row) * NPIX + n0 + cc); \
        } \
        CP_COMMIT(); \
    } while (0)

    PQ_ISSUE(0);
    int dbase = ((lane >> 4) << 3) + (lane & 7);
    int coladd = ((lane >> 3) & 1) * 8;
    for (int kb = 0; kb < 8; kb++) {
        if (kb < 7) { PQ_ISSUE(kb + 1); CP_WAIT1(); } else CP_WAIT0();
        __syncthreads();
        uint32_t base = sb + (kb & 1) * PSTAGE;
        uint32_t wB = base, xB = base + PW_BYTES;
#pragma unroll
        for (int ks = 0; ks < 4; ks++) {
            uint32_t afr[2][4];
#pragma unroll
            for (int mi = 0; mi < 2; mi++) {
                int row = warpM * 32 + mi * 16 + lrow;
                ldm_x4(afr[mi], wB + row * (PW_STRIDE * 2) + ks * 32 + lhalf * 16);
            }
            int drow = ks * 16 + dbase;
#pragma unroll
            for (int ng = 0; ng < 4; ng++) {
                uint32_t bfr[4];
                ldm_x4t(bfr, xB + drow * (PX_STRIDE * 2) + (warpN * 64 + ng * 16 + coladd) * 2);
#pragma unroll
                for (int mi = 0; mi < 2; mi++) {
                    mma16816(acc[mi][2 * ng],     afr[mi], bfr[0], bfr[2]);
                    mma16816(acc[mi][2 * ng + 1], afr[mi], bfr[1], bfr[3]);
                }
            }
        }
        __syncthreads();
    }
#pragma unroll
    for (int mi = 0; mi < 2; mi++) {
        int row_lo = o0 + warpM * 32 + mi * 16 + (lane >> 2);
        int row_hi = row_lo + 8;
        float bl = g_ball[row_lo], bh = g_ball[row_hi];
#pragma unroll
        for (int ni = 0; ni < 8; ni++) {
            int col = n0 + warpN * 64 + ni * 8 + (lane & 3) * 2;
            float v0 = acc[mi][ni][0] + bl, v1 = acc[mi][ni][1] + bl;
            float v2 = acc[mi][ni][2] + bh, v3 = acc[mi][ni][3] + bh;
            // low row
            if (row_lo < 64) {
                __nv_bfloat162 h = __floats2bfloat162_rn(v0, v1);
                *(uint32_t*)(g_qb + ((size_t)b * DK + row_lo) * NPIX + col) = *(uint32_t*)&h;
            } else if (row_lo < 128) {
                __nv_bfloat162 h = __floats2bfloat162_rn(v0, v1);
                *(uint32_t*)(g_kb + ((size_t)b * DK + row_lo - 64) * NPIX + col) = *(uint32_t*)&h;
            } else {
                __half2 h = __floats2half2_rn(v0, v1);
                *(uint32_t*)(g_vh16 + ((size_t)b * CIN + row_lo - 128) * NPIX + col) = *(uint32_t*)&h;
            }
            // high row
            if (row_hi < 64) {
                __nv_bfloat162 h = __floats2bfloat162_rn(v2, v3);
                *(uint32_t*)(g_qb + ((size_t)b * DK + row_hi) * NPIX + col) = *(uint32_t*)&h;
            } else if (row_hi < 128) {
                __nv_bfloat162 h = __floats2bfloat162_rn(v2, v3);
                *(uint32_t*)(g_kb + ((size_t)b * DK + row_hi - 64) * NPIX + col) = *(uint32_t*)&h;
            } else {
                __half2 h = __floats2half2_rn(v2, v3);
                *(uint32_t*)(g_vh16 + ((size_t)b * CIN + row_hi - 128) * NPIX + col) = *(uint32_t*)&h;
            }
        }
    }
}

// ---------------- proj p (xd) fp32 ----------------
__global__ __launch_bounds__(256) void proj_p_kernel(const float* __restrict__ x,
                                                     const float* __restrict__ Wd,
                                                     const float* __restrict__ bd) {
    int b = blockIdx.z;
    int n0 = blockIdx.x * 128;
    const float* B = x + (size_t)b * CIN * NPIX;
    __shared__ float As[8][64];
    __shared__ float Bs[8][128];
    int t = threadIdx.x;
    int tx = t & 15, ty = t >> 4;
    float acc[4][8] = {};
    for (int k0 = 0; k0 < 512; k0 += 8) {
        float4 a4 = make_float4(0.f, 0.f, 0.f, 0.f);
        int arow = t >> 1, akq = (t & 1) * 4;
        if (t < 128) a4 = *(const float4*)&Wd[arow * 512 + k0 + akq];
        int bk = t >> 5, bnq = (t & 31) * 4;
        float4 b4 = *(const float4*)&B[(size_t)(k0 + bk) * NPIX + n0 + bnq];
        __syncthreads();
        if (t < 128) {
            As[akq + 0][arow] = a4.x; As[akq + 1][arow] = a4.y;
            As[akq + 2][arow] = a4.z; As[akq + 3][arow] = a4.w;
        }
        *(float4*)&Bs[bk][bnq] = b4;
        __syncthreads();
#pragma unroll
        for (int k = 0; k < 8; k++) {
            float a[4], bb[8];
#pragma unroll
            for (int i = 0; i < 4; i++) a[i] = As[k][ty * 4 + i];
            *(float4*)&bb[0] = *(float4*)&Bs[k][tx * 8];
            *(float4*)&bb[4] = *(float4*)&Bs[k][tx * 8 + 4];
#pragma unroll
            for (int i = 0; i < 4; i++)
#pragma unroll
                for (int j = 0; j < 8; j++) acc[i][j] += a[i] * bb[j];
        }
    }
#pragma unroll
    for (int i = 0; i < 4; i++) {
        int row = ty * 4 + i;
        float bias = bd[row];
        float* dst = g_p + ((size_t)b * DK + row) * NPIX + n0 + tx * 8;
#pragma unroll
        for (int j = 0; j < 8; j++) dst[j] = acc[i][j] + bias;
    }
}

// ---------------- energy via bf16 HMMA -> fp16 E (round-11 proven: 8 warps) ----------------
__global__ __launch_bounds__(256) void energy_hmma_kernel() {
    __shared__ __align__(16) __nv_bfloat16 Qs[64 * 136];
    __shared__ __align__(16) __nv_bfloat16 Ks[64 * 136];
    int b = blockIdx.z, j0 = blockIdx.x * 128, i0 = blockIdx.y * 128;
    int t = threadIdx.x, lane = t & 31, wid = t >> 5;
    int warpM = wid & 3, warpN = wid >> 2;
    const __nv_bfloat16* qp = g_qb + (size_t)b * DK * NPIX;
    const __nv_bfloat16* kp = g_kb + (size_t)b * DK * NPIX;
    uint32_t sQ = smem_u32(Qs), sK = smem_u32(Ks);
#pragma unroll
    for (int it = 0; it < 4; it++) {
        int g = t + it * 256;
        int row = g >> 4, cc = (g & 15) * 8;
        cp16(sQ + row * 272 + cc * 2, qp + (size_t)row * NPIX + i0 + cc);
        cp16(sK + row * 272 + cc * 2, kp + (size_t)row * NPIX + j0 + cc);
    }
    CP_COMMIT();
    CP_WAIT0();
    __syncthreads();

    float acc[2][8][4] = {};
    int dbase = ((lane >> 4) << 3) + (lane & 7);
    int coladd = ((lane >> 3) & 1) * 8;
#pragma unroll
    for (int ks = 0; ks < 4; ks++) {
        int drow = ks * 16 + dbase;
        uint32_t afr[2][4];
#pragma unroll
        for (int mi = 0; mi < 2; mi++)
            ldm_x4t(afr[mi], sQ + drow * 272 + (warpM * 32 + mi * 16 + coladd) * 2);
#pragma unroll
        for (int ng = 0; ng < 4; ng++) {
            uint32_t bfr[4];
            ldm_x4t(bfr, sK + drow * 272 + (warpN * 64 + ng * 16 + coladd) * 2);
#pragma unroll
            for (int mi = 0; mi < 2; mi++) {
                mma16816(acc[mi][2 * ng],     afr[mi], bfr[0], bfr[2]);
                mma16816(acc[mi][2 * ng + 1], afr[mi], bfr[1], bfr[3]);
            }
        }
    }
    __half* Eb = g_e16 + (size_t)b * NPIX * NPIX;
#pragma unroll
    for (int mi = 0; mi < 2; mi++) {
        int row = i0 + warpM * 32 + mi * 16 + (lane >> 2);
#pragma unroll
        for (int ni = 0; ni < 8; ni++) {
            int col = j0 + warpN * 64 + ni * 8 + (lane & 3) * 2;
            __half2 h0 = __floats2half2_rn(acc[mi][ni][0], acc[mi][ni][1]);
            __half2 h1 = __floats2half2_rn(acc[mi][ni][2], acc[mi][ni][3]);
            *(uint32_t*)&Eb[(size_t)row * NPIX + col]       = *(uint32_t*)&h0;
            *(uint32_t*)&Eb[(size_t)(row + 8) * NPIX + col] = *(uint32_t*)&h1;
        }
    }
}

// ---------------- softmax: fp16 in, fp16 out ----------------
__device__ __forceinline__ float blkRedMax(float v, float* red) {
#pragma unroll
    for (int o = 16; o > 0; o >>= 1) v = fmaxf(v, __shfl_xor_sync(0xffffffffu, v, o));
    if ((threadIdx.x & 31) == 0) red[threadIdx.x >> 5] = v;
    __syncthreads();
    float r = (threadIdx.x < 8) ? red[threadIdx.x] : -1e30f;
    if (threadIdx.x < 32) {
#pragma unroll
        for (int o = 4; o > 0; o >>= 1) r = fmaxf(r, __shfl_xor_sync(0xffffffffu, r, o));
        if (threadIdx.x == 0) red[0] = r;
    }
    __syncthreads();
    float res = red[0];
    __syncthreads();
    return res;
}
__device__ __forceinline__ float blkRedSum(float v, float* red) {
#pragma unroll
    for (int o = 16; o > 0; o >>= 1) v += __shfl_xor_sync(0xffffffffu, v, o);
    if ((threadIdx.x & 31) == 0) red[threadIdx.x >> 5] = v;
    __syncthreads();
    float r = (threadIdx.x < 8) ? red[threadIdx.x] : 0.f;
    if (threadIdx.x < 32) {
#pragma unroll
        for (int o = 4; o > 0; o >>= 1) r += __shfl_xor_sync(0xffffffffu, r, o);
        if (threadIdx.x == 0) red[0] = r;
    }
    __syncthreads();
    float res = red[0];
    __syncthreads();
    return res;
}

__global__ __launch_bounds__(256) void softmax_kernel() {
    int i = blockIdx.x, b = blockIdx.y;
    const __half* row = g_e16 + ((size_t)b * NPIX + i) * NPIX;
    __half* orow = g_attnh + ((size_t)b * NPIX + i) * NPIX;
    int t = threadIdx.x;
    __shared__ float red[8];

    float4 v[4];
    float mx = -1e30f;
#pragma unroll
    for (int j = 0; j < 4; j++) {
        uint2 pk = *(const uint2*)&row[t * 4 + 1024 * j];
        __half2 a = *(__half2*)&pk.x;
        __half2 bq = *(__half2*)&pk.y;
        float2 f0 = __half22float2(a);
        float2 f1 = __half22float2(bq);
        v[j] = make_float4(f0.x, f0.y, f1.x, f1.y);
        mx = fmaxf(mx, fmaxf(fmaxf(v[j].x, v[j].y), fmaxf(v[j].z, v[j].w)));
    }
    float rmax = blkRedMax(mx, red);
    float s = 0.f;
#pragma unroll
    for (int j = 0; j < 4; j++) {
        v[j].x = __expf(v[j].x - rmax); v[j].y = __expf(v[j].y - rmax);
        v[j].z = __expf(v[j].z - rmax); v[j].w = __expf(v[j].w - rmax);
        s += v[j].x + v[j].y + v[j].z + v[j].w;
    }
    float inv = 1.f / blkRedSum(s, red);
#pragma unroll
    for (int j = 0; j < 4; j++) {
        __half2 h0 = __floats2half2_rn(v[j].x * inv, v[j].y * inv);
        __half2 h1 = __floats2half2_rn(v[j].z * inv, v[j].w * inv);
        uint2 pk;
        pk.x = *(uint32_t*)&h0; pk.y = *(uint32_t*)&h1;
        *(uint2*)&orow[t * 4 + 1024 * j] = pk;
    }
}

// ---------------- s_out: round-11 structure, fp16-accumulate HMMA ----------------
#define SO_STRIDE 72
#define SO_TILE   (128 * SO_STRIDE * 2)   // 18432
#define SO_STAGE  (2 * SO_TILE)           // 36864
__global__ __launch_bounds__(256) void sout_kernel(const float* __restrict__ x,
                                                   const float* __restrict__ gamma_s,
                                                   float* __restrict__ out) {
    extern __shared__ __align__(16) char smem[];
    uint32_t sb = smem_u32(smem);
    int b = blockIdx.z;
    int m0 = blockIdx.y * 128;   // m-tile outer
    int c0 = blockIdx.x * 128;   // c-tile inner: adjacent CTAs share attn m-tile via L2
    int t = threadIdx.x, lane = t & 31, wid = t >> 5;
    int warpM = wid & 3, warpN = wid >> 2;
    int lrow = lane & 15, lhalf = lane >> 4;
    const __half* vb = g_vh16  + (size_t)b * CIN  * NPIX;
    const __half* ab = g_attnh + (size_t)b * NPIX * NPIX;
    uint32_t acc[2][8][2] = {};   // fp16x2 accumulators

#define SO_ISSUE(kb) do { \
        uint32_t base = sb + ((kb) & 1) * SO_STAGE; \
        for (int it = 0; it < 4; it++) { \
            int g = t + it * 256; \
            int row = g >> 3, cc = (g & 7) * 8; \
            cp16(base + row * (SO_STRIDE * 2) + cc * 2, \
                 vb + (size_t)(c0 + row) * NPIX + (kb) * 64 + cc); \
        } \
        for (int it = 0; it < 4; it++) { \
            int g = t + it * 256; \
            int row = g >> 3, cc = (g & 7) * 8; \
            cp16(base + SO_TILE + row * (SO_STRIDE * 2) + cc * 2, \
                 ab + (size_t)(m0 + row) * NPIX + (kb) * 64 + cc); \
        } \
        CP_COMMIT(); \
    } while (0)

    SO_ISSUE(0);
    for (int kb = 0; kb < 64; kb++) {
        if (kb < 63) { SO_ISSUE(kb + 1); CP_WAIT1(); } else CP_WAIT0();
        __syncthreads();
        uint32_t base = sb + (kb & 1) * SO_STAGE;
        uint32_t aB = base, bB = base + SO_TILE;
#pragma unroll
        for (int ks = 0; ks < 4; ks++) {
            uint32_t afr[2][4];
#pragma unroll
            for (int mi = 0; mi < 2; mi++) {
                int row = warpM * 32 + mi * 16 + lrow;
                ldm_x4(afr[mi], aB + row * (SO_STRIDE * 2) + ks * 32 + lhalf * 16);
            }
#pragma unroll
            for (int ng = 0; ng < 4; ng++) {
                int row = warpN * 64 + ng * 16 + lrow;
                uint32_t bfr[4];
                ldm_x4(bfr, bB + row * (SO_STRIDE * 2) + ks * 32 + lhalf * 16);
#pragma unroll
                for (int mi = 0; mi < 2; mi++) {
                    mma16816h(acc[mi][2 * ng],     afr[mi], bfr[0], bfr[2]);
                    mma16816h(acc[mi][2 * ng + 1], afr[mi], bfr[1], bfr[3]);
                }
            }
        }
        __syncthreads();
    }

    float gs = *gamma_s;
    const float* xb = x   + (size_t)b * CIN * NPIX;
    float*       ob = out + (size_t)b * CIN * NPIX;
#pragma unroll
    for (int mi = 0; mi < 2; mi++) {
        int row = c0 + warpM * 32 + mi * 16 + (lane >> 2);
#pragma unroll
        for (int ni = 0; ni < 8; ni++) {
            int col = m0 + warpN * 64 + ni * 8 + (lane & 3) * 2;
            float2 f01 = __half22float2(*(__half2*)&acc[mi][ni][0]);
            float2 f23 = __half22float2(*(__half2*)&acc[mi][ni][1]);
            size_t i0 = (size_t)row * NPIX + col;
            float2 x0 = *(const float2*)&xb[i0];
            float2 o0 = make_float2(gs * f01.x + x0.x, gs * f01.y + x0.y);
            *(float2*)&ob[i0] = o0;
            size_t i1 = i0 + (size_t)8 * NPIX;
            float2 x1 = *(const float2*)&xb[i1];
            float2 o1 = make_float2(gs * f23.x + x1.x, gs * f23.y + x1.y);
            *(float2*)&ob[i1] = o1;
        }
    }
}

// ---------------- chan_e: e partials (fp32), 32 N-splits ----------------
__global__ __launch_bounds__(256) void chan_e_kernel() {
    int b = blockIdx.y, kb = blockIdx.x;
    const float* p = g_p + (size_t)b * DK * NPIX;
    __shared__ float sp[64][65];
    int t = threadIdx.x;
    int tx = t & 15, ty = t >> 4;
    float acc[4][4] = {};
    for (int ch = 0; ch < 2; ch++) {
        int base = kb * 128 + ch * 64;
        __syncthreads();
#pragma unroll
        for (int i = 0; i < 16; i++) {
            int lin = t + 256 * i;
            int r = lin >> 6, c = lin & 63;
            sp[c][r] = p[(size_t)r * NPIX + base + c];
        }
        __syncthreads();
#pragma unroll 8
        for (int k = 0; k < 64; k++) {
            float a[4], bb[4];
#pragma unroll
            for (int i = 0; i < 4; i++) a[i]  = sp[k][ty * 4 + i];
#pragma unroll
            for (int j = 0; j < 4; j++) bb[j] = sp[k][tx * 4 + j];
#pragma unroll
            for (int i = 0; i < 4; i++)
#pragma unroll
                for (int j = 0; j < 4; j++) acc[i][j] += a[i] * bb[j];
        }
    }
#pragma unroll
    for (int i = 0; i < 4; i++)
#pragma unroll
        for (int j = 0; j < 4; j++)
            g_epart[(((size_t)kb * BAT + b) * DK + ty * 4 + i) * DK + tx * 4 + j] = acc[i][j];
}

// ---------------- chanfinal: cattn softmax + cf + Wu GEMM + out+=, fused ----------------
#define CF_CA   0
#define CF_BUF  16640
#define CF_CF   (16640 + 33792)
#define CF_SMEM (16640 + 33792 + 33792)
__global__ __launch_bounds__(256) void chanfinal_kernel(const float* __restrict__ Wu,
                                                        const float* __restrict__ bu,
                                                        const float* __restrict__ gamma_c,
                                                        float* __restrict__ out) {
    extern __shared__ __align__(16) char cs[];
    float* ca  = (float*)(cs + CF_CA);
    float* buf = (float*)(cs + CF_BUF);
    float* cf  = (float*)(cs + CF_CF);
    int b = blockIdx.y;
    int n0 = blockIdx.x * 128;
    int t = threadIdx.x;
    int w = t >> 5, lane = t & 31;
    const float* p = g_p + (size_t)b * DK * NPIX;

    for (int r = w * 8; r < w * 8 + 8; r++) {
        float v0 = 0.f, v1 = 0.f;
        for (int kb = 0; kb < NSPL; kb++) {
            const float* ep = &g_epart[(((size_t)kb * BAT + b) * DK + r) * DK];
            v0 += ep[lane];
            v1 += ep[lane + 32];
        }
        float mn = fminf(v0, v1);
#pragma unroll
        for (int o = 16; o > 0; o >>= 1) mn = fminf(mn, __shfl_xor_sync(0xffffffffu, mn, o));
        float z0 = __expf(mn - v0), z1 = __expf(mn - v1);
        float s = z0 + z1;
#pragma unroll
        for (int o = 16; o > 0; o >>= 1) s += __shfl_xor_sync(0xffffffffu, s, o);
        float inv = 1.f / s;
        ca[lane * 65 + r]        = z0 * inv;
        ca[(lane + 32) * 65 + r] = z1 * inv;
    }
    for (int i = t; i < 64 * 128; i += 256) {
        int d = i >> 7, n = i & 127;
        buf[d * 132 + n] = p[(size_t)d * NPIX + n0 + n];
    }
    __syncthreads();
    {
        int tx = t & 15, ty = t >> 4;
        float acc[4][8] = {};
        for (int k = 0; k < 64; k++) {
            float a[4], bb[8];
#pragma unroll
            for (int i = 0; i < 4; i++) a[i] = ca[k * 65 + ty * 4 + i];
#pragma unroll
            for (int j = 0; j < 8; j++) bb[j] = buf[k * 132 + tx * 8 + j];
#pragma unroll
            for (int i = 0; i < 4; i++)
#pragma unroll
                for (int j = 0; j < 8; j++) acc[i][j] += a[i] * bb[j];
        }
        float gc = *gamma_c;
#pragma unroll
        for (int i = 0; i < 4; i++) {
            int c = ty * 4 + i;
#pragma unroll
            for (int j = 0; j < 8; j++) {
                int n = tx * 8 + j;
                cf[c * 132 + n] = gc * acc[i][j] + buf[c * 132 + n];
            }
        }
    }
    __syncthreads();
    for (int ch = 0; ch < 4; ch++) {
        for (int i = t; i < 128 * 64; i += 256) {
            int o = i >> 6, k = i & 63;
            buf[k * 132 + o] = Wu[(size_t)(ch * 128 + o) * DK + k];
        }
        __syncthreads();
        int tx = t & 15, ty = t >> 4;
        float acc[8][8] = {};
        for (int k = 0; k < 64; k++) {
            float a[8], bb[8];
#pragma unroll
            for (int i = 0; i < 8; i++) a[i]  = buf[k * 132 + ty * 8 + i];
#pragma unroll
            for (int j = 0; j < 8; j++) bb[j] = cf[k * 132 + tx * 8 + j];
#pragma unroll
            for (int i = 0; i < 8; i++)
#pragma unroll
                for (int j = 0; j < 8; j++) acc[i][j] += a[i] * bb[j];
        }
#pragma unroll
        for (int i = 0; i < 8; i++) {
            int o = ch * 128 + ty * 8 + i;
            float bias = bu[o];
            size_t base = ((size_t)b * CIN + o) * NPIX + n0 + tx * 8;
            float4 c0 = *(float4*)&out[base];
            float4 c1 = *(float4*)&out[base + 4];
            c0.x += acc[i][0] + bias; c0.y += acc[i][1] + bias;
            c0.z += acc[i][2] + bias; c0.w += acc[i][3] + bias;
            c1.x += acc[i][4] + bias; c1.y += acc[i][5] + bias;
            c1.z += acc[i][6] + bias; c1.w += acc[i][7] + bias;
            *(float4*)&out[base]     = c0;
            *(float4*)&out[base + 4] = c1;
        }
        __syncthreads();
    }
}

// ---------------- launch ----------------
extern "C" void kernel_launch(void* const* d_in, const int* in_sizes, int n_in,
                              void* d_out, int out_size) {
    const float* x  = (const float*)d_in[0];
    const float* Wq = (const float*)d_in[1];
    const float* bq = (const float*)d_in[2];
    const float* Wk = (const float*)d_in[3];
    const float* bk = (const float*)d_in[4];
    const float* Wv = (const float*)d_in[5];
    const float* bv = (const float*)d_in[6];
    const float* gs = (const float*)d_in[7];
    const float* Wd = (const float*)d_in[8];
    const float* bd = (const float*)d_in[9];
    const float* Wu = (const float*)d_in[10];
    const float* bu = (const float*)d_in[11];
    const float* gc = (const float*)d_in[12];
    float* out = (float*)d_out;

    cudaFuncSetAttribute(projqkv_kernel, cudaFuncAttributeMaxDynamicSharedMemorySize, 2 * PSTAGE);
    cudaFuncSetAttribute(sout_kernel, cudaFuncAttributeMaxDynamicSharedMemorySize, 2 * SO_STAGE);
    cudaFuncSetAttribute(chanfinal_kernel, cudaFuncAttributeMaxDynamicSharedMemorySize, CF_SMEM);

    packx_kernel<<<8192, 256>>>(x, Wq, bq, Wk, bk, Wv, bv);
    proj_p_kernel<<<dim3(32, 1, BAT), 256>>>(x, Wd, bd);
    projqkv_kernel<<<dim3(32, 5, BAT), 256, 2 * PSTAGE>>>();
    chan_e_kernel<<<dim3(NSPL, BAT), 256>>>();
    energy_hmma_kernel<<<dim3(32, 32, BAT), 256>>>();
    softmax_kernel<<<dim3(NPIX, BAT), 256>>>();
    sout_kernel<<<dim3(4, 32, BAT), 256, 2 * SO_STAGE>>>(x, gs, out);
    chanfinal_kernel<<<dim3(32, BAT), 256, CF_SMEM>>>(Wu, bu, gc, out);
}